// round 5
// baseline (speedup 1.0000x reference)
#include <cuda_runtime.h>
#include <cuda_bf16.h>
#include <math.h>

// ---------------- Problem constants ----------------
#define NREF 131072
#define NALT 32768
#define BSEG 4096
#define DDIM 128
#define FDIM 512
#define HDIM 256
#define LN_EPS 1e-5f

typedef unsigned int u32;

// ---------------- Scratch (device globals) ----------------
__device__ u32 g_z1_ref[(size_t)NREF * 128];   // bf16x2 pairs (256 cols)
__device__ u32 g_z2_ref[(size_t)NREF * 128];
__device__ u32 g_z1_alt[(size_t)NALT * 128];
__device__ u32 g_z2_alt[(size_t)NALT * 128];
__device__ float g_sum_ref[BSEG * HDIM];
__device__ float g_sum_alt[BSEG * HDIM];
__device__ float g_cnt_ref[BSEG];
__device__ float g_cnt_alt[BSEG];
__device__ float g_cref[BSEG * HDIM];
__device__ float g_calt[BSEG * HDIM];

// ---------------- Helpers ----------------
__device__ __forceinline__ u32 pkbf(float lo, float hi) {
    u32 r;
    asm("cvt.rn.bf16x2.f32 %0, %1, %2;" : "=r"(r) : "f"(hi), "f"(lo));
    return r;
}
__device__ __forceinline__ float2 upbf(u32 v) {
    union { u32 u; __nv_bfloat162 h; } cv;
    cv.u = v;
    return __bfloat1622float2(cv.h);
}
__device__ __forceinline__ void mma_bf16(float* c, const u32* a, u32 b0, u32 b1) {
    asm volatile(
        "mma.sync.aligned.m16n8k16.row.col.f32.bf16.bf16.f32 "
        "{%0,%1,%2,%3}, {%4,%5,%6,%7}, {%8,%9}, {%0,%1,%2,%3};"
        : "+f"(c[0]), "+f"(c[1]), "+f"(c[2]), "+f"(c[3])
        : "r"(a[0]), "r"(a[1]), "r"(a[2]), "r"(a[3]), "r"(b0), "r"(b1));
}
__device__ __forceinline__ void ldsm4(u32& r0, u32& r1, u32& r2, u32& r3, u32 addr) {
    asm volatile("ldmatrix.sync.aligned.m8n8.x4.shared.b16 {%0,%1,%2,%3}, [%4];"
                 : "=r"(r0), "=r"(r1), "=r"(r2), "=r"(r3) : "r"(addr));
}
__device__ __forceinline__ u32 s2u(const void* p) {
    return (u32)__cvta_generic_to_shared(p);
}
__device__ __forceinline__ float warp_sum(float v) {
#pragma unroll
    for (int o = 16; o > 0; o >>= 1) v += __shfl_xor_sync(0xffffffffu, v, o);
    return v;
}
__device__ __forceinline__ float selu_f(float x) {
    const float sc = 1.0507009873554805f;
    const float al = 1.6732632423543772f;
    return x > 0.f ? sc * x : sc * al * (expf(x) - 1.f);
}

// ---------------- Kernel 0: zero accumulators ----------------
__global__ void zero_kernel(float* __restrict__ s1, float* __restrict__ s2,
                            float* __restrict__ c1, float* __restrict__ c2) {
    int i = blockIdx.x * blockDim.x + threadIdx.x;
    if (i < BSEG * HDIM) { s1[i] = 0.f; s2[i] = 0.f; }
    if (i < BSEG)        { c1[i] = 0.f; c2[i] = 0.f; }
}

// ---------------- Kernel 1: merged persistent LN1+GEMM1+SELU+LN2+segsum ---
// 512 threads (16 warps). W1 bf16 resident in smem. Tile = 64 rows.
#define SW1_U (512 * 68)
#define SA_U  (64 * 68)
#define SZ_U  (64 * 132)
#define SM1_BYTES ((SW1_U + SA_U + SZ_U) * 4 + 64 * 8 * 2 * 4 + 64 * 4)

__global__ void __launch_bounds__(512, 1)
fwd1_kernel(const float* __restrict__ xr, const int* __restrict__ segr,
            const float* __restrict__ w1r, const float* __restrict__ b1rp,
            u32* __restrict__ z1r, u32* __restrict__ z2r,
            float* __restrict__ sumr, float* __restrict__ cntr, int ntr,
            const float* __restrict__ xa, const int* __restrict__ sega,
            const float* __restrict__ w1a, const float* __restrict__ b1ap,
            u32* __restrict__ z1a, u32* __restrict__ z2a,
            float* __restrict__ suma, float* __restrict__ cnta, int nta,
            const float* __restrict__ n1w, const float* __restrict__ n1b,
            const float* __restrict__ n2w, const float* __restrict__ n2b,
            int nblk_ref) {
    extern __shared__ float smf[];
    u32* sw = (u32*)smf;              // [512 n][68] bf16 k-pairs of W1
    u32* sa = sw + SW1_U;             // [64 m][68]  bf16 k-pairs of LN1(x)
    u32* sz = sa + SA_U;              // [64 m][132] bf16 col-pairs staging
    float* ps = (float*)(sz + SZ_U);  // [64][8] LN2 partial sums
    float* pq = ps + 64 * 8;          // [64][8] LN2 partial sumsq
    int*   ssg = (int*)(pq + 64 * 8); // [64]

    // ---- stream selection (ref vs alt)
    const float* x;  const int* seg;  const float* w1;  const float* b1;
    u32 *z1out, *z2out;  float *segsum, *segcnt;
    int bid, nblk, ntiles;
    if (blockIdx.x < nblk_ref) {
        x = xr; seg = segr; w1 = w1r; b1 = b1rp;
        z1out = z1r; z2out = z2r; segsum = sumr; segcnt = cntr;
        bid = blockIdx.x; nblk = nblk_ref; ntiles = ntr;
    } else {
        x = xa; seg = sega; w1 = w1a; b1 = b1ap;
        z1out = z1a; z2out = z2a; segsum = suma; segcnt = cnta;
        bid = blockIdx.x - nblk_ref; nblk = gridDim.x - nblk_ref; ntiles = nta;
    }

    const int tid = threadIdx.x;
    const int lane = tid & 31;
    const int wid = tid >> 5;
    const int g = lane >> 2;
    const int t = lane & 3;
    const int wm = wid & 1;    // row half (32 rows)
    const int wn = wid >> 1;   // 8 col-groups of 32
    const int lr = lane & 7;
    const int ls = lane >> 3;

    // ---- stage W1 (f32 gmem -> bf16-pair smem), once
    for (int i = tid; i < 64 * 512; i += 512) {
        int kp = i >> 9;
        int n = i & 511;
        float v0 = __ldg(w1 + (size_t)(2 * kp) * FDIM + n);
        float v1 = __ldg(w1 + (size_t)(2 * kp + 1) * FDIM + n);
        sw[n * 68 + kp] = pkbf(v0, v1);
    }

    // ---- ldmatrix byte base addresses
    u32 a_base[2], b_base[2];
#pragma unroll
    for (int mt = 0; mt < 2; mt++)
        a_base[mt] = s2u(sa) + ((wm * 32 + mt * 16 + (ls & 1) * 8 + lr) * 68 + (ls >> 1) * 4) * 4;
#pragma unroll
    for (int p = 0; p < 2; p++)
        b_base[p] = s2u(sw) + ((wn * 32 + 16 * p + (ls >> 1) * 8 + lr) * 68 + (ls & 1) * 4) * 4;

    // ---- hoist per-thread constants
    float4 wv = __ldg(((const float4*)n1w) + lane);
    float4 bv = __ldg(((const float4*)n1b) + lane);
    float b1r_[2][4][2], w2r[4][2], b2r[4][2];
#pragma unroll
    for (int c = 0; c < 2; c++)
#pragma unroll
        for (int nt = 0; nt < 4; nt++) {
            int col = c * 256 + wn * 32 + nt * 8 + 2 * t;
            b1r_[c][nt][0] = __ldg(b1 + col);
            b1r_[c][nt][1] = __ldg(b1 + col + 1);
        }
#pragma unroll
    for (int nt = 0; nt < 4; nt++) {
        int col = wn * 32 + nt * 8 + 2 * t;
        w2r[nt][0] = __ldg(n2w + col);  w2r[nt][1] = __ldg(n2w + col + 1);
        b2r[nt][0] = __ldg(n2b + col);  b2r[nt][1] = __ldg(n2b + col + 1);
    }
    __syncthreads();

    for (int tile = bid; tile < ntiles; tile += nblk) {
        const int row0 = tile * 64;
        if (tid < 64) ssg[tid] = __ldg(seg + row0 + tid);

        // ---- LN1 -> sa (each warp: 4 rows)
#pragma unroll
        for (int rr = 0; rr < 4; rr++) {
            int rl = wid * 4 + rr;
            float4 xv = __ldg((const float4*)(x + (size_t)(row0 + rl) * DDIM) + lane);
            float s  = warp_sum(xv.x + xv.y + xv.z + xv.w);
            float sq = warp_sum(xv.x * xv.x + xv.y * xv.y + xv.z * xv.z + xv.w * xv.w);
            float m = s * (1.f / 128.f);
            float inv = rsqrtf(sq * (1.f / 128.f) - m * m + LN_EPS);
            float y0 = (xv.x - m) * inv * wv.x + bv.x;
            float y1 = (xv.y - m) * inv * wv.y + bv.y;
            float y2 = (xv.z - m) * inv * wv.z + bv.z;
            float y3 = (xv.w - m) * inv * wv.w + bv.w;
            *(uint2*)(sa + rl * 68 + lane * 2) = make_uint2(pkbf(y0, y1), pkbf(y2, y3));
        }
        __syncthreads();

        // ---- two N-chunks of 256: c=0 -> z1, c=1 -> z2(+LN2)
#pragma unroll 1
        for (int c = 0; c < 2; c++) {
            float acc[2][4][4];
#pragma unroll
            for (int mt = 0; mt < 2; mt++)
#pragma unroll
                for (int nt = 0; nt < 4; nt++)
#pragma unroll
                    for (int j = 0; j < 4; j++) acc[mt][nt][j] = 0.f;

            const u32 cb = (u32)(c * 256 * 68 * 4);
#pragma unroll
            for (int k0 = 0; k0 < 128; k0 += 16) {
                u32 a0[4], a1[4], bA[4], bB[4];
                ldsm4(a0[0], a0[1], a0[2], a0[3], a_base[0] + k0 * 2);
                ldsm4(a1[0], a1[1], a1[2], a1[3], a_base[1] + k0 * 2);
                ldsm4(bA[0], bA[1], bA[2], bA[3], b_base[0] + cb + k0 * 2);
                ldsm4(bB[0], bB[1], bB[2], bB[3], b_base[1] + cb + k0 * 2);
                mma_bf16(acc[0][0], a0, bA[0], bA[1]);
                mma_bf16(acc[1][0], a1, bA[0], bA[1]);
                mma_bf16(acc[0][1], a0, bA[2], bA[3]);
                mma_bf16(acc[1][1], a1, bA[2], bA[3]);
                mma_bf16(acc[0][2], a0, bB[0], bB[1]);
                mma_bf16(acc[1][2], a1, bB[0], bB[1]);
                mma_bf16(acc[0][3], a0, bB[2], bB[3]);
                mma_bf16(acc[1][3], a1, bB[2], bB[3]);
            }

            // bias + SELU in place
#pragma unroll
            for (int mt = 0; mt < 2; mt++)
#pragma unroll
                for (int nt = 0; nt < 4; nt++) {
                    acc[mt][nt][0] = selu_f(acc[mt][nt][0] + b1r_[c][nt][0]);
                    acc[mt][nt][1] = selu_f(acc[mt][nt][1] + b1r_[c][nt][1]);
                    acc[mt][nt][2] = selu_f(acc[mt][nt][2] + b1r_[c][nt][0]);
                    acc[mt][nt][3] = selu_f(acc[mt][nt][3] + b1r_[c][nt][1]);
                }

            if (c == 0) {
                // z1: pack to sz, flush coalesced as bf16 pairs
#pragma unroll
                for (int mt = 0; mt < 2; mt++)
#pragma unroll
                    for (int nt = 0; nt < 4; nt++) {
                        int r = wm * 32 + mt * 16 + g;
                        int c2 = wn * 16 + nt * 4 + t;
                        sz[r * 132 + c2]       = pkbf(acc[mt][nt][0], acc[mt][nt][1]);
                        sz[(r + 8) * 132 + c2] = pkbf(acc[mt][nt][2], acc[mt][nt][3]);
                    }
                __syncthreads();
                for (int i = tid; i < 64 * 128; i += 512) {
                    int r = i >> 7, c2 = i & 127;
                    z1out[((size_t)(row0 + r) << 7) + c2] = sz[r * 132 + c2];
                }
                __syncthreads();
            } else {
                // z2: LN2 (cross-warp row reduction), pack, flush, then segsum
                float s[2][2], q[2][2];
#pragma unroll
                for (int mt = 0; mt < 2; mt++) {
                    s[mt][0] = s[mt][1] = q[mt][0] = q[mt][1] = 0.f;
#pragma unroll
                    for (int nt = 0; nt < 4; nt++) {
                        s[mt][0] += acc[mt][nt][0] + acc[mt][nt][1];
                        q[mt][0] += acc[mt][nt][0] * acc[mt][nt][0] + acc[mt][nt][1] * acc[mt][nt][1];
                        s[mt][1] += acc[mt][nt][2] + acc[mt][nt][3];
                        q[mt][1] += acc[mt][nt][2] * acc[mt][nt][2] + acc[mt][nt][3] * acc[mt][nt][3];
                    }
                }
#pragma unroll
                for (int off = 1; off <= 2; off <<= 1)
#pragma unroll
                    for (int mt = 0; mt < 2; mt++)
#pragma unroll
                        for (int h = 0; h < 2; h++) {
                            s[mt][h] += __shfl_xor_sync(0xffffffffu, s[mt][h], off);
                            q[mt][h] += __shfl_xor_sync(0xffffffffu, q[mt][h], off);
                        }
                if (t == 0) {
#pragma unroll
                    for (int mt = 0; mt < 2; mt++)
#pragma unroll
                        for (int h = 0; h < 2; h++) {
                            int r = wm * 32 + mt * 16 + g + 8 * h;
                            ps[r * 8 + wn] = s[mt][h];
                            pq[r * 8 + wn] = q[mt][h];
                        }
                }
                __syncthreads();
                float mean[2][2], inv[2][2];
#pragma unroll
                for (int mt = 0; mt < 2; mt++)
#pragma unroll
                    for (int h = 0; h < 2; h++) {
                        int r = wm * 32 + mt * 16 + g + 8 * h;
                        float S = 0.f, Q = 0.f;
#pragma unroll
                        for (int w = 0; w < 8; w++) { S += ps[r * 8 + w]; Q += pq[r * 8 + w]; }
                        float m = S * (1.f / 256.f);
                        mean[mt][h] = m;
                        inv[mt][h] = rsqrtf(Q * (1.f / 256.f) - m * m + LN_EPS);
                    }
#pragma unroll
                for (int mt = 0; mt < 2; mt++)
#pragma unroll
                    for (int nt = 0; nt < 4; nt++) {
                        int r = wm * 32 + mt * 16 + g;
                        int c2 = wn * 16 + nt * 4 + t;
                        float y0 = (acc[mt][nt][0] - mean[mt][0]) * inv[mt][0] * w2r[nt][0] + b2r[nt][0];
                        float y1 = (acc[mt][nt][1] - mean[mt][0]) * inv[mt][0] * w2r[nt][1] + b2r[nt][1];
                        float y2 = (acc[mt][nt][2] - mean[mt][1]) * inv[mt][1] * w2r[nt][0] + b2r[nt][0];
                        float y3 = (acc[mt][nt][3] - mean[mt][1]) * inv[mt][1] * w2r[nt][1] + b2r[nt][1];
                        sz[r * 132 + c2]       = pkbf(y0, y1);
                        sz[(r + 8) * 132 + c2] = pkbf(y2, y3);
                    }
                __syncthreads();
                for (int i = tid; i < 64 * 128; i += 512) {
                    int r = i >> 7, c2 = i & 127;
                    z2out[((size_t)(row0 + r) << 7) + c2] = sz[r * 132 + c2];
                }
            }
        }

        // ---- segment sums from sz (z2), run-length aggregated (seg sorted)
        {
            int grp = tid >> 8;         // 0,1 -> rows 0-31 / 32-63
            int col = tid & 255;
            int rb = grp * 32;
            float accv = 0.f, cnt = 0.f;
            int cur = ssg[rb];
#pragma unroll 1
            for (int r = rb; r < rb + 32; r++) {
                int sv = ssg[r];
                if (sv != cur) {
                    atomicAdd(&segsum[(size_t)cur * HDIM + col], accv);
                    if (col == 0) atomicAdd(&segcnt[cur], cnt);
                    accv = 0.f; cnt = 0.f; cur = sv;
                }
                float2 pv = upbf(sz[r * 132 + (col >> 1)]);
                accv += (col & 1) ? pv.y : pv.x;
                cnt += 1.f;
            }
            atomicAdd(&segsum[(size_t)cur * HDIM + col], accv);
            if (col == 0) atomicAdd(&segcnt[cur], cnt);
        }
        __syncthreads();
    }
}

// ---------------- Kernel 2: per-(batch,h) gate coefficients ----------------
// One block per segment; reciprocals hoisted (no per-element division).
__global__ void coeff_kernel(const float* __restrict__ sum_r, const float* __restrict__ cnt_r,
                             const float* __restrict__ sum_a, const float* __restrict__ cnt_a,
                             const float* __restrict__ ref_reg, const float* __restrict__ reg_w_pre,
                             const float* __restrict__ beta_ref, const float* __restrict__ beta_alt,
                             const float* __restrict__ gamma,
                             float* __restrict__ cref, float* __restrict__ calt) {
    int b = blockIdx.x;
    int h = threadIdx.x;
    float rw = expf(reg_w_pre[0]) + 0.25f;
    float rcr = 1.f / (__ldg(cnt_r + b) + rw);
    float rca = 1.f / fmaxf(__ldg(cnt_a + b), 1.f);
    int idx = (b << 8) + h;
    float rmf = (__ldg(sum_r + idx) + rw * __ldg(ref_reg + h)) * rcr;
    float amf = __ldg(sum_a + idx) * rca;
    cref[idx] = beta_ref[0] * rmf;
    calt[idx] = beta_alt[0] * amf + gamma[0] * rmf;
}

// ---------------- Kernel 3: merged persistent gate+GEMM2+residual ---------
// 512 threads, 2 CTA/SM. W2 bf16 resident. Tile = 64 rows.
#define SW2_U (128 * 132)
#define SG_U  (64 * 132)
#define SM2_BYTES ((SW2_U + SG_U) * 4 + 64 * 4)

__global__ void __launch_bounds__(512, 2)
fwd2_kernel(const float* __restrict__ xr, const int* __restrict__ segr,
            const u32* __restrict__ z1r, const u32* __restrict__ z2r,
            const float* __restrict__ ctabr, const float* __restrict__ alphar,
            const float* __restrict__ w2rp, const float* __restrict__ b2rp,
            float* __restrict__ outr, int ntr,
            const float* __restrict__ xa, const int* __restrict__ sega,
            const u32* __restrict__ z1a, const u32* __restrict__ z2a,
            const float* __restrict__ ctaba, const float* __restrict__ alphaa,
            const float* __restrict__ w2ap, const float* __restrict__ b2ap,
            float* __restrict__ outa, int nta,
            int nblk_ref) {
    extern __shared__ float smf[];
    u32* sw = (u32*)smf;            // [128 n][132] bf16 k-pairs of W2
    u32* sg = sw + SW2_U;           // [64 m][132]  gated activations
    int* ssg = (int*)(sg + SG_U);   // [64]

    const float* x; const int* seg; const u32 *z1, *z2;
    const float *ctab, *alpha_p, *w2, *b2;
    float* out;
    int bid, nblk, ntiles;
    if (blockIdx.x < nblk_ref) {
        x = xr; seg = segr; z1 = z1r; z2 = z2r; ctab = ctabr; alpha_p = alphar;
        w2 = w2rp; b2 = b2rp; out = outr;
        bid = blockIdx.x; nblk = nblk_ref; ntiles = ntr;
    } else {
        x = xa; seg = sega; z1 = z1a; z2 = z2a; ctab = ctaba; alpha_p = alphaa;
        w2 = w2ap; b2 = b2ap; out = outa;
        bid = blockIdx.x - nblk_ref; nblk = gridDim.x - nblk_ref; ntiles = nta;
    }

    const int tid = threadIdx.x;
    const int lane = tid & 31;
    const int wid = tid >> 5;
    const int g = lane >> 2;
    const int t = lane & 3;
    const int wm = wid & 3;    // 4 row-groups of 16
    const int wn = wid >> 2;   // 4 col-groups of 32
    const int lr = lane & 7;
    const int ls = lane >> 3;

    // stage W2 (f32 gmem -> bf16-pair smem), once
    for (int i = tid; i < 128 * 128; i += 512) {
        int kp = i >> 7;
        int n = i & 127;
        float v0 = __ldg(w2 + (size_t)(2 * kp) * DDIM + n);
        float v1 = __ldg(w2 + (size_t)(2 * kp + 1) * DDIM + n);
        sw[n * 132 + kp] = pkbf(v0, v1);
    }

    u32 a_base = s2u(sg) + ((wm * 16 + (ls & 1) * 8 + lr) * 132 + (ls >> 1) * 4) * 4;
    u32 b_base[2];
#pragma unroll
    for (int p = 0; p < 2; p++)
        b_base[p] = s2u(sw) + ((wn * 32 + 16 * p + (ls >> 1) * 8 + lr) * 132 + (ls & 1) * 4) * 4;

    float b2r[4][2];
#pragma unroll
    for (int nt = 0; nt < 4; nt++) {
        int col = wn * 32 + nt * 8 + 2 * t;
        b2r[nt][0] = __ldg(b2 + col);
        b2r[nt][1] = __ldg(b2 + col + 1);
    }
    const float alpha = __ldg(alpha_p);
    __syncthreads();

    const float2* ctab2 = (const float2*)ctab;
    const float2* x2 = (const float2*)x;
    float2* out2 = (float2*)out;

    for (int tile = bid; tile < ntiles; tile += nblk) {
        const int row0 = tile * 64;
        if (tid < 64) ssg[tid] = __ldg(seg + row0 + tid);
        __syncthreads();

        // build gated activations -> sg (bf16 pairs)
#pragma unroll 4
        for (int i = tid; i < 64 * 128; i += 512) {
            int r = i >> 7, c2 = i & 127;
            size_t gidx = ((size_t)(row0 + r) << 7) + c2;
            float2 z1f = upbf(__ldg(z1 + gidx));
            float2 z2f = upbf(__ldg(z2 + gidx));
            float2 cc = __ldg(ctab2 + ((size_t)ssg[r] << 7) + c2);
            float g0 = z1f.x * fmaf(z2f.x, alpha, 1.f + cc.x);
            float g1 = z1f.y * fmaf(z2f.y, alpha, 1.f + cc.y);
            sg[r * 132 + c2] = pkbf(g0, g1);
        }
        __syncthreads();

        // GEMM: out[64][128] = g[64][256] @ W2, warp tile 16x32
        float acc[4][4];
#pragma unroll
        for (int nt = 0; nt < 4; nt++)
#pragma unroll
            for (int j = 0; j < 4; j++) acc[nt][j] = 0.f;

#pragma unroll
        for (int k0 = 0; k0 < 256; k0 += 16) {
            u32 a[4], bA[4], bB[4];
            ldsm4(a[0], a[1], a[2], a[3], a_base + k0 * 2);
            ldsm4(bA[0], bA[1], bA[2], bA[3], b_base[0] + k0 * 2);
            ldsm4(bB[0], bB[1], bB[2], bB[3], b_base[1] + k0 * 2);
            mma_bf16(acc[0], a, bA[0], bA[1]);
            mma_bf16(acc[1], a, bA[2], bA[3]);
            mma_bf16(acc[2], a, bB[0], bB[1]);
            mma_bf16(acc[3], a, bB[2], bB[3]);
        }

        // epilogue: residual + bias
#pragma unroll
        for (int nt = 0; nt < 4; nt++) {
            int col2 = (wn * 32 + nt * 8 + 2 * t) >> 1;
            size_t rowA = (size_t)(row0 + wm * 16 + g);
            size_t rowB = rowA + 8;
            float2 xa2 = __ldg(x2 + rowA * 64 + col2);
            float2 xb2 = __ldg(x2 + rowB * 64 + col2);
            float2 oa, ob;
            oa.x = xa2.x + acc[nt][0] + b2r[nt][0];
            oa.y = xa2.y + acc[nt][1] + b2r[nt][1];
            ob.x = xb2.x + acc[nt][2] + b2r[nt][0];
            ob.y = xb2.y + acc[nt][3] + b2r[nt][1];
            out2[rowA * 64 + col2] = oa;
            out2[rowB * 64 + col2] = ob;
        }
        __syncthreads();
    }
}

// ---------------- Launch ----------------
extern "C" void kernel_launch(void* const* d_in, const int* in_sizes, int n_in,
                              void* d_out, int out_size) {
    const float* ref_flat = (const float*)d_in[0];
    const float* alt_flat = (const float*)d_in[1];
    const int*   ref_seg  = (const int*)d_in[2];
    const int*   alt_seg  = (const int*)d_in[3];
    const float* norm1_w  = (const float*)d_in[4];
    const float* norm1_b  = (const float*)d_in[5];
    const float* w1_ref   = (const float*)d_in[6];
    const float* b1_ref   = (const float*)d_in[7];
    const float* w1_alt   = (const float*)d_in[8];
    const float* b1_alt   = (const float*)d_in[9];
    const float* norm2_w  = (const float*)d_in[10];
    const float* norm2_b  = (const float*)d_in[11];
    const float* alpha_ref = (const float*)d_in[12];
    const float* alpha_alt = (const float*)d_in[13];
    const float* beta_ref  = (const float*)d_in[14];
    const float* beta_alt  = (const float*)d_in[15];
    const float* gamma     = (const float*)d_in[16];
    const float* ref_regularizer = (const float*)d_in[17];
    const float* reg_w_pre = (const float*)d_in[18];
    const float* w2_ref    = (const float*)d_in[19];
    const float* b2_ref    = (const float*)d_in[20];
    const float* w2_alt    = (const float*)d_in[21];
    const float* b2_alt    = (const float*)d_in[22];

    float* out_r = (float*)d_out;
    float* out_a = out_r + (size_t)NREF * DDIM;

    u32 *pz1r, *pz2r, *pz1a, *pz2a;
    float *psr, *psa, *pcr, *pca, *pcref, *pcalt;
    cudaGetSymbolAddress((void**)&pz1r, g_z1_ref);
    cudaGetSymbolAddress((void**)&pz2r, g_z2_ref);
    cudaGetSymbolAddress((void**)&pz1a, g_z1_alt);
    cudaGetSymbolAddress((void**)&pz2a, g_z2_alt);
    cudaGetSymbolAddress((void**)&psr,  g_sum_ref);
    cudaGetSymbolAddress((void**)&psa,  g_sum_alt);
    cudaGetSymbolAddress((void**)&pcr,  g_cnt_ref);
    cudaGetSymbolAddress((void**)&pca,  g_cnt_alt);
    cudaGetSymbolAddress((void**)&pcref, g_cref);
    cudaGetSymbolAddress((void**)&pcalt, g_calt);

    int sm_count = 148;
    cudaDeviceGetAttribute(&sm_count, cudaDevAttrMultiProcessorCount, 0);

    cudaFuncSetAttribute(fwd1_kernel, cudaFuncAttributeMaxDynamicSharedMemorySize, SM1_BYTES);
    cudaFuncSetAttribute(fwd2_kernel, cudaFuncAttributeMaxDynamicSharedMemorySize, SM2_BYTES);

    zero_kernel<<<(BSEG * HDIM + 255) / 256, 256>>>(psr, psa, pcr, pca);

    // merged fwd1: ref blocks : alt blocks = 4 : 1 (work ratio 2048 : 512)
    int g1 = sm_count;
    int nbr1 = (g1 * 4) / 5;
    fwd1_kernel<<<g1, 512, SM1_BYTES>>>(
        ref_flat, ref_seg, w1_ref, b1_ref, pz1r, pz2r, psr, pcr, NREF / 64,
        alt_flat, alt_seg, w1_alt, b1_alt, pz1a, pz2a, psa, pca, NALT / 64,
        norm1_w, norm1_b, norm2_w, norm2_b, nbr1);

    coeff_kernel<<<BSEG, 256>>>(psr, pcr, psa, pca,
                                ref_regularizer, reg_w_pre,
                                beta_ref, beta_alt, gamma,
                                pcref, pcalt);

    int g2 = 2 * sm_count;
    int nbr2 = (g2 * 4) / 5;
    fwd2_kernel<<<g2, 512, SM2_BYTES>>>(
        ref_flat, ref_seg, pz1r, pz2r, pcref, alpha_ref, w2_ref, b2_ref, out_r, NREF / 64,
        alt_flat, alt_seg, pz1a, pz2a, pcalt, alpha_alt, w2_alt, b2_alt, out_a, NALT / 64,
        nbr2);
}

// round 6
// speedup vs baseline: 1.3604x; 1.3604x over previous
#include <cuda_runtime.h>
#include <cuda_bf16.h>
#include <math.h>

// ---------------- Problem constants ----------------
#define NREF 131072
#define NALT 32768
#define BSEG 4096
#define DDIM 128
#define FDIM 512
#define HDIM 256
#define LN_EPS 1e-5f

typedef unsigned int u32;

// ---------------- Scratch (device globals) ----------------
__device__ u32 g_z1_ref[(size_t)NREF * 128];   // bf16x2 pairs (256 cols)
__device__ u32 g_z2_ref[(size_t)NREF * 128];
__device__ u32 g_z1_alt[(size_t)NALT * 128];
__device__ u32 g_z2_alt[(size_t)NALT * 128];
__device__ float g_sum_ref[BSEG * HDIM];
__device__ float g_sum_alt[BSEG * HDIM];
__device__ float g_cnt_ref[BSEG];
__device__ float g_cnt_alt[BSEG];
__device__ float g_cref[BSEG * HDIM];
__device__ float g_calt[BSEG * HDIM];

// ---------------- Helpers ----------------
__device__ __forceinline__ u32 pkbf(float lo, float hi) {
    u32 r;
    asm("cvt.rn.bf16x2.f32 %0, %1, %2;" : "=r"(r) : "f"(hi), "f"(lo));
    return r;
}
__device__ __forceinline__ float2 upbf(u32 v) {
    union { u32 u; __nv_bfloat162 h; } cv;
    cv.u = v;
    return __bfloat1622float2(cv.h);
}
__device__ __forceinline__ void mma_bf16(float* c, const u32* a, u32 b0, u32 b1) {
    asm volatile(
        "mma.sync.aligned.m16n8k16.row.col.f32.bf16.bf16.f32 "
        "{%0,%1,%2,%3}, {%4,%5,%6,%7}, {%8,%9}, {%0,%1,%2,%3};"
        : "+f"(c[0]), "+f"(c[1]), "+f"(c[2]), "+f"(c[3])
        : "r"(a[0]), "r"(a[1]), "r"(a[2]), "r"(a[3]), "r"(b0), "r"(b1));
}
__device__ __forceinline__ u32 s2u(const void* p) {
    return (u32)__cvta_generic_to_shared(p);
}
__device__ __forceinline__ void cp16(u32 smem_dst, const void* gsrc) {
    asm volatile("cp.async.cg.shared.global [%0], [%1], 16;"
                 :: "r"(smem_dst), "l"(gsrc));
}
__device__ __forceinline__ void cp_commit() {
    asm volatile("cp.async.commit_group;");
}
__device__ __forceinline__ void cp_wait0() {
    asm volatile("cp.async.wait_group 0;");
}
__device__ __forceinline__ float warp_sum(float v) {
#pragma unroll
    for (int o = 16; o > 0; o >>= 1) v += __shfl_xor_sync(0xffffffffu, v, o);
    return v;
}
__device__ __forceinline__ float selu_f(float x) {
    const float sc = 1.0507009873554805f;
    const float al = 1.6732632423543772f;
    return x > 0.f ? sc * x : sc * al * (expf(x) - 1.f);
}

// ---------------- Kernel 0: zero accumulators ----------------
__global__ void zero_kernel(float* __restrict__ s1, float* __restrict__ s2,
                            float* __restrict__ c1, float* __restrict__ c2) {
    int i = blockIdx.x * blockDim.x + threadIdx.x;
    if (i < BSEG * HDIM) { s1[i] = 0.f; s2[i] = 0.f; }
    if (i < BSEG)        { c1[i] = 0.f; c2[i] = 0.f; }
}

// ---------------- Kernel 1: persistent LN1+GEMM1+SELU+LN2+segsum ----------
// 512 threads (16 warps). W1 bf16 resident in smem. Tile = 64 rows.
// x prefetched one tile ahead via cp.async into sx.
#define SW1_U (512 * 68)
#define SA_U  (64 * 68)
#define SZ_U  (64 * 132)
#define SX_U  (64 * 132)
#define SM1_BYTES ((SW1_U + SA_U + SZ_U + SX_U) * 4 + 64 * 8 * 2 * 4 + 64 * 4)

__global__ void __launch_bounds__(512, 1)
fwd1_kernel(const float* __restrict__ x, const int* __restrict__ seg,
            const float* __restrict__ n1w, const float* __restrict__ n1b,
            const float* __restrict__ w1, const float* __restrict__ b1,
            const float* __restrict__ n2w, const float* __restrict__ n2b,
            u32* __restrict__ z1out, u32* __restrict__ z2out,
            float* __restrict__ segsum, float* __restrict__ segcnt,
            int ntiles) {
    extern __shared__ float smf[];
    u32* sw = (u32*)smf;              // [512 n][68] bf16 k-pairs of W1
    u32* sa = sw + SW1_U;             // [64 m][68]  bf16 k-pairs of LN1(x)
    u32* sz = sa + SA_U;              // [64 m][132] bf16 col-pairs staging
    float* sx = (float*)(sz + SZ_U);  // [64 m][132] prefetched x (f32)
    float* ps = sx + SX_U;            // [64][8] LN2 partial sums
    float* pq = ps + 64 * 8;          // [64][8] LN2 partial sumsq
    int*   ssg = (int*)(pq + 64 * 8); // [64]

    const int tid = threadIdx.x;
    const int lane = tid & 31;
    const int wid = tid >> 5;
    const int g = lane >> 2;
    const int t = lane & 3;
    const int wm = wid & 1;    // row half (32 rows)
    const int wn = wid >> 1;   // 8 col-groups of 32

    // ---- stage W1 (f32 gmem -> bf16-pair smem), once
    for (int i = tid; i < 64 * 512; i += 512) {
        int kp = i >> 9;
        int n = i & 511;
        float v0 = __ldg(w1 + (size_t)(2 * kp) * FDIM + n);
        float v1 = __ldg(w1 + (size_t)(2 * kp + 1) * FDIM + n);
        sw[n * 68 + kp] = pkbf(v0, v1);
    }

    // ---- hoist per-thread constants
    float4 wv = __ldg(((const float4*)n1w) + lane);
    float4 bv = __ldg(((const float4*)n1b) + lane);
    float b1r[2][4][2], w2r[4][2], b2r[4][2];
#pragma unroll
    for (int c = 0; c < 2; c++)
#pragma unroll
        for (int nt = 0; nt < 4; nt++) {
            int col = c * 256 + wn * 32 + nt * 8 + 2 * t;
            b1r[c][nt][0] = __ldg(b1 + col);
            b1r[c][nt][1] = __ldg(b1 + col + 1);
        }
#pragma unroll
    for (int nt = 0; nt < 4; nt++) {
        int col = wn * 32 + nt * 8 + 2 * t;
        w2r[nt][0] = __ldg(n2w + col);  w2r[nt][1] = __ldg(n2w + col + 1);
        b2r[nt][0] = __ldg(n2b + col);  b2r[nt][1] = __ldg(n2b + col + 1);
    }

    // ---- prefetch first tile's x into sx
    {
        int tile0 = blockIdx.x;
        if (tile0 < ntiles) {
            const float4* src = (const float4*)(x + (size_t)tile0 * 64 * DDIM);
#pragma unroll
            for (int q = 0; q < 4; q++) {
                int i = q * 512 + tid;             // 0..2047 float4s
                int r = i >> 5, j = i & 31;
                cp16(s2u(sx) + (u32)((r * 132 + j * 4) * 4), src + r * 32 + j);
            }
        }
        cp_commit();
    }
    __syncthreads();

    for (int tile = blockIdx.x; tile < ntiles; tile += gridDim.x) {
        const int row0 = tile * 64;
        if (tid < 64) ssg[tid] = __ldg(seg + row0 + tid);

        // ---- wait for prefetched x, barrier for cross-thread visibility
        cp_wait0();
        __syncthreads();

        // ---- LN1 from sx -> sa (each warp: 4 rows)
#pragma unroll
        for (int rr = 0; rr < 4; rr++) {
            int rl = wid * 4 + rr;
            float4 xv = *(const float4*)&sx[rl * 132 + lane * 4];
            float s  = warp_sum(xv.x + xv.y + xv.z + xv.w);
            float sq = warp_sum(xv.x * xv.x + xv.y * xv.y + xv.z * xv.z + xv.w * xv.w);
            float m = s * (1.f / 128.f);
            float inv = rsqrtf(sq * (1.f / 128.f) - m * m + LN_EPS);
            float y0 = (xv.x - m) * inv * wv.x + bv.x;
            float y1 = (xv.y - m) * inv * wv.y + bv.y;
            float y2 = (xv.z - m) * inv * wv.z + bv.z;
            float y3 = (xv.w - m) * inv * wv.w + bv.w;
            *(uint2*)(sa + rl * 68 + lane * 2) = make_uint2(pkbf(y0, y1), pkbf(y2, y3));
        }
        __syncthreads();

        // ---- issue prefetch for next tile (lands during GEMM)
        {
            int nxt = tile + gridDim.x;
            if (nxt < ntiles) {
                const float4* src = (const float4*)(x + (size_t)nxt * 64 * DDIM);
#pragma unroll
                for (int q = 0; q < 4; q++) {
                    int i = q * 512 + tid;
                    int r = i >> 5, j = i & 31;
                    cp16(s2u(sx) + (u32)((r * 132 + j * 4) * 4), src + r * 32 + j);
                }
            }
            cp_commit();
        }

        // ---- two N-chunks of 256: c=0 -> z1, c=1 -> z2(+LN2)
#pragma unroll 1
        for (int c = 0; c < 2; c++) {
            float acc[2][4][4];
#pragma unroll
            for (int mt = 0; mt < 2; mt++)
#pragma unroll
                for (int nt = 0; nt < 4; nt++)
#pragma unroll
                    for (int j = 0; j < 4; j++) acc[mt][nt][j] = 0.f;

            const int nb = c * 256 + wn * 32;
#pragma unroll
            for (int k0 = 0; k0 < 128; k0 += 16) {
                const int kp = k0 >> 1;
                u32 a[2][4];
#pragma unroll
                for (int mt = 0; mt < 2; mt++) {
                    const u32* pa = sa + (wm * 32 + mt * 16 + g) * 68 + kp + t;
                    a[mt][0] = pa[0];
                    a[mt][2] = pa[4];
                    a[mt][1] = pa[8 * 68];
                    a[mt][3] = pa[8 * 68 + 4];
                }
#pragma unroll
                for (int nt = 0; nt < 4; nt++) {
                    const u32* pb = sw + (nb + nt * 8 + g) * 68 + kp + t;
                    u32 b0 = pb[0], b1v = pb[4];
                    mma_bf16(acc[0][nt], a[0], b0, b1v);
                    mma_bf16(acc[1][nt], a[1], b0, b1v);
                }
            }

            // bias + SELU in place
#pragma unroll
            for (int mt = 0; mt < 2; mt++)
#pragma unroll
                for (int nt = 0; nt < 4; nt++) {
                    acc[mt][nt][0] = selu_f(acc[mt][nt][0] + b1r[c][nt][0]);
                    acc[mt][nt][1] = selu_f(acc[mt][nt][1] + b1r[c][nt][1]);
                    acc[mt][nt][2] = selu_f(acc[mt][nt][2] + b1r[c][nt][0]);
                    acc[mt][nt][3] = selu_f(acc[mt][nt][3] + b1r[c][nt][1]);
                }

            if (c == 0) {
                // z1: pack to sz, flush coalesced as uint2
#pragma unroll
                for (int mt = 0; mt < 2; mt++)
#pragma unroll
                    for (int nt = 0; nt < 4; nt++) {
                        int r = wm * 32 + mt * 16 + g;
                        int c2 = wn * 16 + nt * 4 + t;
                        sz[r * 132 + c2]       = pkbf(acc[mt][nt][0], acc[mt][nt][1]);
                        sz[(r + 8) * 132 + c2] = pkbf(acc[mt][nt][2], acc[mt][nt][3]);
                    }
                __syncthreads();
                for (int i = tid; i < 64 * 64; i += 512) {
                    int r = i >> 6, cc = i & 63;
                    ((uint2*)z1out)[((size_t)(row0 + r) << 6) + cc] =
                        *(const uint2*)&sz[r * 132 + 2 * cc];
                }
                __syncthreads();
            } else {
                // z2: LN2 (cross-warp row reduction), pack, flush, then segsum
                float s[2][2], q[2][2];
#pragma unroll
                for (int mt = 0; mt < 2; mt++) {
                    s[mt][0] = s[mt][1] = q[mt][0] = q[mt][1] = 0.f;
#pragma unroll
                    for (int nt = 0; nt < 4; nt++) {
                        s[mt][0] += acc[mt][nt][0] + acc[mt][nt][1];
                        q[mt][0] += acc[mt][nt][0] * acc[mt][nt][0] + acc[mt][nt][1] * acc[mt][nt][1];
                        s[mt][1] += acc[mt][nt][2] + acc[mt][nt][3];
                        q[mt][1] += acc[mt][nt][2] * acc[mt][nt][2] + acc[mt][nt][3] * acc[mt][nt][3];
                    }
                }
#pragma unroll
                for (int off = 1; off <= 2; off <<= 1)
#pragma unroll
                    for (int mt = 0; mt < 2; mt++)
#pragma unroll
                        for (int h = 0; h < 2; h++) {
                            s[mt][h] += __shfl_xor_sync(0xffffffffu, s[mt][h], off);
                            q[mt][h] += __shfl_xor_sync(0xffffffffu, q[mt][h], off);
                        }
                if (t == 0) {
#pragma unroll
                    for (int mt = 0; mt < 2; mt++)
#pragma unroll
                        for (int h = 0; h < 2; h++) {
                            int r = wm * 32 + mt * 16 + g + 8 * h;
                            ps[r * 8 + wn] = s[mt][h];
                            pq[r * 8 + wn] = q[mt][h];
                        }
                }
                __syncthreads();
                float mean[2][2], inv[2][2];
#pragma unroll
                for (int mt = 0; mt < 2; mt++)
#pragma unroll
                    for (int h = 0; h < 2; h++) {
                        int r = wm * 32 + mt * 16 + g + 8 * h;
                        float S = 0.f, Q = 0.f;
#pragma unroll
                        for (int w = 0; w < 8; w++) { S += ps[r * 8 + w]; Q += pq[r * 8 + w]; }
                        float m = S * (1.f / 256.f);
                        mean[mt][h] = m;
                        inv[mt][h] = rsqrtf(Q * (1.f / 256.f) - m * m + LN_EPS);
                    }
#pragma unroll
                for (int mt = 0; mt < 2; mt++)
#pragma unroll
                    for (int nt = 0; nt < 4; nt++) {
                        int r = wm * 32 + mt * 16 + g;
                        int c2 = wn * 16 + nt * 4 + t;
                        float y0 = (acc[mt][nt][0] - mean[mt][0]) * inv[mt][0] * w2r[nt][0] + b2r[nt][0];
                        float y1 = (acc[mt][nt][1] - mean[mt][0]) * inv[mt][0] * w2r[nt][1] + b2r[nt][1];
                        float y2 = (acc[mt][nt][2] - mean[mt][1]) * inv[mt][1] * w2r[nt][0] + b2r[nt][0];
                        float y3 = (acc[mt][nt][3] - mean[mt][1]) * inv[mt][1] * w2r[nt][1] + b2r[nt][1];
                        sz[r * 132 + c2]       = pkbf(y0, y1);
                        sz[(r + 8) * 132 + c2] = pkbf(y2, y3);
                    }
                __syncthreads();
                for (int i = tid; i < 64 * 64; i += 512) {
                    int r = i >> 6, cc = i & 63;
                    ((uint2*)z2out)[((size_t)(row0 + r) << 6) + cc] =
                        *(const uint2*)&sz[r * 132 + 2 * cc];
                }
            }
        }

        // ---- segment sums from sz (z2), run-length aggregated (seg sorted)
        {
            int grp = tid >> 8;         // 0,1 -> rows 0-31 / 32-63
            int col = tid & 255;
            int rb = grp * 32;
            float accv = 0.f, cnt = 0.f;
            int cur = ssg[rb];
#pragma unroll 1
            for (int r = rb; r < rb + 32; r++) {
                int sv = ssg[r];
                if (sv != cur) {
                    atomicAdd(&segsum[(size_t)cur * HDIM + col], accv);
                    if (col == 0) atomicAdd(&segcnt[cur], cnt);
                    accv = 0.f; cnt = 0.f; cur = sv;
                }
                float2 pv = upbf(sz[r * 132 + (col >> 1)]);
                accv += (col & 1) ? pv.y : pv.x;
                cnt += 1.f;
            }
            atomicAdd(&segsum[(size_t)cur * HDIM + col], accv);
            if (col == 0) atomicAdd(&segcnt[cur], cnt);
        }
        __syncthreads();
    }
}

// ---------------- Kernel 2: per-(batch,h) gate coefficients ----------------
// One block per segment; reciprocals hoisted.
__global__ void coeff_kernel(const float* __restrict__ sum_r, const float* __restrict__ cnt_r,
                             const float* __restrict__ sum_a, const float* __restrict__ cnt_a,
                             const float* __restrict__ ref_reg, const float* __restrict__ reg_w_pre,
                             const float* __restrict__ beta_ref, const float* __restrict__ beta_alt,
                             const float* __restrict__ gamma,
                             float* __restrict__ cref, float* __restrict__ calt) {
    int b = blockIdx.x;
    int h = threadIdx.x;
    float rw = expf(reg_w_pre[0]) + 0.25f;
    float rcr = 1.f / (__ldg(cnt_r + b) + rw);
    float rca = 1.f / fmaxf(__ldg(cnt_a + b), 1.f);
    int idx = (b << 8) + h;
    float rmf = (__ldg(sum_r + idx) + rw * __ldg(ref_reg + h)) * rcr;
    float amf = __ldg(sum_a + idx) * rca;
    cref[idx] = beta_ref[0] * rmf;
    calt[idx] = beta_alt[0] * amf + gamma[0] * rmf;
}

// ---------------- Kernel 3: persistent gate+GEMM2+residual ----------------
// 512 threads, 2 CTA/SM. W2 bf16 resident. Tile = 64 rows.
#define SW2_U (128 * 132)
#define SG_U  (64 * 132)
#define SM2_BYTES ((SW2_U + SG_U) * 4 + 64 * 4)

__global__ void __launch_bounds__(512, 2)
fwd2_kernel(const float* __restrict__ x, const int* __restrict__ seg,
            const u32* __restrict__ z1, const u32* __restrict__ z2,
            const float* __restrict__ ctab, const float* __restrict__ alpha_p,
            const float* __restrict__ w2, const float* __restrict__ b2,
            float* __restrict__ out, int ntiles) {
    extern __shared__ float smf[];
    u32* sw = (u32*)smf;            // [128 n][132] bf16 k-pairs of W2
    u32* sg = sw + SW2_U;           // [64 m][132]  gated activations
    int* ssg = (int*)(sg + SG_U);   // [64]

    const int tid = threadIdx.x;
    const int lane = tid & 31;
    const int wid = tid >> 5;
    const int g = lane >> 2;
    const int t = lane & 3;
    const int wm = wid & 3;    // 4 row-groups of 16
    const int wn = wid >> 2;   // 4 col-groups of 32

    // stage W2 (f32 gmem -> bf16-pair smem), once
    for (int i = tid; i < 128 * 128; i += 512) {
        int kp = i >> 7;
        int n = i & 127;
        float v0 = __ldg(w2 + (size_t)(2 * kp) * DDIM + n);
        float v1 = __ldg(w2 + (size_t)(2 * kp + 1) * DDIM + n);
        sw[n * 132 + kp] = pkbf(v0, v1);
    }
    float b2r[4][2];
#pragma unroll
    for (int nt = 0; nt < 4; nt++) {
        int col = wn * 32 + nt * 8 + 2 * t;
        b2r[nt][0] = __ldg(b2 + col);
        b2r[nt][1] = __ldg(b2 + col + 1);
    }
    const float alpha = __ldg(alpha_p);
    __syncthreads();

    const uint2* z1v2 = (const uint2*)z1;
    const uint2* z2v2 = (const uint2*)z2;
    const float4* ctab4 = (const float4*)ctab;
    const float2* x2 = (const float2*)x;
    float2* out2 = (float2*)out;

    for (int tile = blockIdx.x; tile < ntiles; tile += gridDim.x) {
        const int row0 = tile * 64;
        if (tid < 64) ssg[tid] = __ldg(seg + row0 + tid);
        __syncthreads();

        // build gated activations -> sg (bf16 pairs), uint2 width
#pragma unroll 4
        for (int i = tid; i < 64 * 64; i += 512) {
            int r = i >> 6, cc = i & 63;
            size_t gidx = ((size_t)(row0 + r) << 6) + cc;
            uint2 z1p = __ldg(z1v2 + gidx);
            uint2 z2p = __ldg(z2v2 + gidx);
            float4 c4 = __ldg(ctab4 + (((size_t)ssg[r]) << 6) + cc);
            float2 z1a = upbf(z1p.x), z1b = upbf(z1p.y);
            float2 z2a = upbf(z2p.x), z2b = upbf(z2p.y);
            float g0 = z1a.x * fmaf(z2a.x, alpha, 1.f + c4.x);
            float g1 = z1a.y * fmaf(z2a.y, alpha, 1.f + c4.y);
            float g2 = z1b.x * fmaf(z2b.x, alpha, 1.f + c4.z);
            float g3 = z1b.y * fmaf(z2b.y, alpha, 1.f + c4.w);
            *(uint2*)&sg[r * 132 + 2 * cc] = make_uint2(pkbf(g0, g1), pkbf(g2, g3));
        }
        __syncthreads();

        // GEMM: out[64][128] = g[64][256] @ W2, warp tile 16x32
        float acc[4][4];
#pragma unroll
        for (int nt = 0; nt < 4; nt++)
#pragma unroll
            for (int j = 0; j < 4; j++) acc[nt][j] = 0.f;

#pragma unroll
        for (int k0 = 0; k0 < 256; k0 += 16) {
            const int kp = k0 >> 1;
            u32 a[4];
            const u32* pa = sg + (wm * 16 + g) * 132 + kp + t;
            a[0] = pa[0];
            a[2] = pa[4];
            a[1] = pa[8 * 132];
            a[3] = pa[8 * 132 + 4];
#pragma unroll
            for (int nt = 0; nt < 4; nt++) {
                const u32* pb = sw + (wn * 32 + nt * 8 + g) * 132 + kp + t;
                mma_bf16(acc[nt], a, pb[0], pb[4]);
            }
        }

        // epilogue: residual + bias
#pragma unroll
        for (int nt = 0; nt < 4; nt++) {
            int col2 = (wn * 32 + nt * 8 + 2 * t) >> 1;
            size_t rowA = (size_t)(row0 + wm * 16 + g);
            size_t rowB = rowA + 8;
            float2 xa = __ldg(x2 + rowA * 64 + col2);
            float2 xb = __ldg(x2 + rowB * 64 + col2);
            float2 oa, ob;
            oa.x = xa.x + acc[nt][0] + b2r[nt][0];
            oa.y = xa.y + acc[nt][1] + b2r[nt][1];
            ob.x = xb.x + acc[nt][2] + b2r[nt][0];
            ob.y = xb.y + acc[nt][3] + b2r[nt][1];
            out2[rowA * 64 + col2] = oa;
            out2[rowB * 64 + col2] = ob;
        }
        __syncthreads();
    }
}

// ---------------- Launch ----------------
extern "C" void kernel_launch(void* const* d_in, const int* in_sizes, int n_in,
                              void* d_out, int out_size) {
    const float* ref_flat = (const float*)d_in[0];
    const float* alt_flat = (const float*)d_in[1];
    const int*   ref_seg  = (const int*)d_in[2];
    const int*   alt_seg  = (const int*)d_in[3];
    const float* norm1_w  = (const float*)d_in[4];
    const float* norm1_b  = (const float*)d_in[5];
    const float* w1_ref   = (const float*)d_in[6];
    const float* b1_ref   = (const float*)d_in[7];
    const float* w1_alt   = (const float*)d_in[8];
    const float* b1_alt   = (const float*)d_in[9];
    const float* norm2_w  = (const float*)d_in[10];
    const float* norm2_b  = (const float*)d_in[11];
    const float* alpha_ref = (const float*)d_in[12];
    const float* alpha_alt = (const float*)d_in[13];
    const float* beta_ref  = (const float*)d_in[14];
    const float* beta_alt  = (const float*)d_in[15];
    const float* gamma     = (const float*)d_in[16];
    const float* ref_regularizer = (const float*)d_in[17];
    const float* reg_w_pre = (const float*)d_in[18];
    const float* w2_ref    = (const float*)d_in[19];
    const float* b2_ref    = (const float*)d_in[20];
    const float* w2_alt    = (const float*)d_in[21];
    const float* b2_alt    = (const float*)d_in[22];

    float* out_r = (float*)d_out;
    float* out_a = out_r + (size_t)NREF * DDIM;

    u32 *pz1r, *pz2r, *pz1a, *pz2a;
    float *psr, *psa, *pcr, *pca, *pcref, *pcalt;
    cudaGetSymbolAddress((void**)&pz1r, g_z1_ref);
    cudaGetSymbolAddress((void**)&pz2r, g_z2_ref);
    cudaGetSymbolAddress((void**)&pz1a, g_z1_alt);
    cudaGetSymbolAddress((void**)&pz2a, g_z2_alt);
    cudaGetSymbolAddress((void**)&psr,  g_sum_ref);
    cudaGetSymbolAddress((void**)&psa,  g_sum_alt);
    cudaGetSymbolAddress((void**)&pcr,  g_cnt_ref);
    cudaGetSymbolAddress((void**)&pca,  g_cnt_alt);
    cudaGetSymbolAddress((void**)&pcref, g_cref);
    cudaGetSymbolAddress((void**)&pcalt, g_calt);

    int sm_count = 148;
    cudaDeviceGetAttribute(&sm_count, cudaDevAttrMultiProcessorCount, 0);

    cudaFuncSetAttribute(fwd1_kernel, cudaFuncAttributeMaxDynamicSharedMemorySize, SM1_BYTES);
    cudaFuncSetAttribute(fwd2_kernel, cudaFuncAttributeMaxDynamicSharedMemorySize, SM2_BYTES);

    zero_kernel<<<(BSEG * HDIM + 255) / 256, 256>>>(psr, psa, pcr, pca);

    fwd1_kernel<<<sm_count, 512, SM1_BYTES>>>(ref_flat, ref_seg, norm1_w, norm1_b,
                                              w1_ref, b1_ref, norm2_w, norm2_b,
                                              pz1r, pz2r, psr, pcr, NREF / 64);
    fwd1_kernel<<<sm_count, 512, SM1_BYTES>>>(alt_flat, alt_seg, norm1_w, norm1_b,
                                              w1_alt, b1_alt, norm2_w, norm2_b,
                                              pz1a, pz2a, psa, pca, NALT / 64);

    coeff_kernel<<<BSEG, 256>>>(psr, pcr, psa, pca,
                                ref_regularizer, reg_w_pre,
                                beta_ref, beta_alt, gamma,
                                pcref, pcalt);

    fwd2_kernel<<<2 * sm_count, 512, SM2_BYTES>>>(ref_flat, ref_seg, pz1r, pz2r,
                                                  pcref, alpha_ref, w2_ref, b2_ref,
                                                  out_r, NREF / 64);
    fwd2_kernel<<<2 * sm_count, 512, SM2_BYTES>>>(alt_flat, alt_seg, pz1a, pz2a,
                                                  pcalt, alpha_alt, w2_alt, b2_alt,
                                                  out_a, NALT / 64);
}

// round 7
// speedup vs baseline: 1.3635x; 1.0023x over previous
#include <cuda_runtime.h>
#include <cuda_bf16.h>
#include <math.h>

// ---------------- Problem constants ----------------
#define NREF 131072
#define NALT 32768
#define BSEG 4096
#define DDIM 128
#define FDIM 512
#define HDIM 256
#define LN_EPS 1e-5f

typedef unsigned int u32;

// ---------------- Scratch (device globals) ----------------
__device__ u32 g_z1_ref[(size_t)NREF * 128];   // bf16x2 pairs (256 cols)
__device__ u32 g_z2_ref[(size_t)NREF * 128];
__device__ u32 g_z1_alt[(size_t)NALT * 128];
__device__ u32 g_z2_alt[(size_t)NALT * 128];
__device__ float g_sum_ref[BSEG * HDIM];
__device__ float g_sum_alt[BSEG * HDIM];
__device__ float g_cnt_ref[BSEG];
__device__ float g_cnt_alt[BSEG];
__device__ float g_cref[BSEG * HDIM];
__device__ float g_calt[BSEG * HDIM];

// ---------------- Helpers ----------------
__device__ __forceinline__ u32 pkbf(float lo, float hi) {
    u32 r;
    asm("cvt.rn.bf16x2.f32 %0, %1, %2;" : "=r"(r) : "f"(hi), "f"(lo));
    return r;
}
__device__ __forceinline__ float2 upbf(u32 v) {
    union { u32 u; __nv_bfloat162 h; } cv;
    cv.u = v;
    return __bfloat1622float2(cv.h);
}
__device__ __forceinline__ void mma_bf16(float* c, const u32* a, u32 b0, u32 b1) {
    asm volatile(
        "mma.sync.aligned.m16n8k16.row.col.f32.bf16.bf16.f32 "
        "{%0,%1,%2,%3}, {%4,%5,%6,%7}, {%8,%9}, {%0,%1,%2,%3};"
        : "+f"(c[0]), "+f"(c[1]), "+f"(c[2]), "+f"(c[3])
        : "r"(a[0]), "r"(a[1]), "r"(a[2]), "r"(a[3]), "r"(b0), "r"(b1));
}
__device__ __forceinline__ u32 s2u(const void* p) {
    return (u32)__cvta_generic_to_shared(p);
}
__device__ __forceinline__ void cp16(u32 smem_dst, const void* gsrc) {
    asm volatile("cp.async.cg.shared.global [%0], [%1], 16;"
                 :: "r"(smem_dst), "l"(gsrc));
}
__device__ __forceinline__ void cp_commit() {
    asm volatile("cp.async.commit_group;");
}
__device__ __forceinline__ void cp_wait0() {
    asm volatile("cp.async.wait_group 0;");
}
__device__ __forceinline__ float warp_sum(float v) {
#pragma unroll
    for (int o = 16; o > 0; o >>= 1) v += __shfl_xor_sync(0xffffffffu, v, o);
    return v;
}
__device__ __forceinline__ float selu_f(float x) {
    const float sc = 1.0507009873554805f;
    const float al = 1.6732632423543772f;
    return x > 0.f ? sc * x : sc * al * (expf(x) - 1.f);
}

// ---------------- Kernel 0: zero accumulators ----------------
__global__ void zero_kernel(float* __restrict__ s1, float* __restrict__ s2,
                            float* __restrict__ c1, float* __restrict__ c2) {
    int i = blockIdx.x * blockDim.x + threadIdx.x;
    if (i < BSEG * HDIM) { s1[i] = 0.f; s2[i] = 0.f; }
    if (i < BSEG)        { c1[i] = 0.f; c2[i] = 0.f; }
}

// ---------------- Kernel 1: split-class persistent LN1+GEMM1 --------------
// 2 CTAs/SM. Even blocks: z1 half (W1 cols 0-255). Odd blocks: z2 half
// (cols 256-511) + LN2 + segsum. Tile = 32 rows, 512 threads.
#define SW1_U (256 * 68)
#define SA_U  (32 * 68)
#define SZ_U  (32 * 130)
#define SX_U  (32 * 132)
#define SM1_BYTES ((SW1_U + SA_U + SZ_U + SX_U + 32 * 8 * 2) * 4 + 32 * 4)

__global__ void __launch_bounds__(512, 2)
fwd1_kernel(const float* __restrict__ x, const int* __restrict__ seg,
            const float* __restrict__ n1w, const float* __restrict__ n1b,
            const float* __restrict__ w1, const float* __restrict__ b1,
            const float* __restrict__ n2w, const float* __restrict__ n2b,
            u32* __restrict__ z1out, u32* __restrict__ z2out,
            float* __restrict__ segsum, float* __restrict__ segcnt,
            int ntiles) {
    extern __shared__ float smf[];
    u32* sw = (u32*)smf;              // [256 n][68] bf16 k-pairs of W1 half
    u32* sa = sw + SW1_U;             // [32 m][68]  bf16 k-pairs of LN1(x)
    u32* sz = sa + SA_U;              // [32 m][130] bf16 col-pairs staging
    float* sx = (float*)(sz + SZ_U);  // [32 m][132] prefetched x (f32)
    float* ps = sx + SX_U;            // [32][8] LN2 partial sums
    float* pq = ps + 32 * 8;          // [32][8] LN2 partial sumsq
    int*   ssg = (int*)(pq + 32 * 8); // [32]

    const int zcls = blockIdx.x & 1;       // 0 -> z1 half, 1 -> z2 half
    const int bidc = blockIdx.x >> 1;
    const int nblk = gridDim.x >> 1;

    const int tid = threadIdx.x;
    const int lane = tid & 31;
    const int wid = tid >> 5;
    const int g = lane >> 2;
    const int t = lane & 3;
    const int wm = wid & 1;    // 2 row-groups of 16
    const int wn = wid >> 1;   // 8 col-groups of 32

    // ---- stage this class's W1 half (f32 gmem -> bf16-pair smem), once
    for (int i = tid; i < 64 * 256; i += 512) {
        int kp = i >> 8;
        int n = i & 255;
        float v0 = __ldg(w1 + (size_t)(2 * kp) * FDIM + zcls * 256 + n);
        float v1 = __ldg(w1 + (size_t)(2 * kp + 1) * FDIM + zcls * 256 + n);
        sw[n * 68 + kp] = pkbf(v0, v1);
    }

    // ---- hoist per-thread constants
    float4 wv = __ldg(((const float4*)n1w) + lane);
    float4 bv = __ldg(((const float4*)n1b) + lane);
    float b1r[4][2], w2r[4][2], b2r[4][2];
#pragma unroll
    for (int nt = 0; nt < 4; nt++) {
        int col = zcls * 256 + wn * 32 + nt * 8 + 2 * t;
        b1r[nt][0] = __ldg(b1 + col);
        b1r[nt][1] = __ldg(b1 + col + 1);
        int h = wn * 32 + nt * 8 + 2 * t;
        w2r[nt][0] = __ldg(n2w + h);  w2r[nt][1] = __ldg(n2w + h + 1);
        b2r[nt][0] = __ldg(n2b + h);  b2r[nt][1] = __ldg(n2b + h + 1);
    }

    u32* zout = zcls ? z2out : z1out;

    // ---- prefetch first tile's x into sx (32 rows x 128 f32 = 1024 float4)
    {
        int tile0 = bidc;
        if (tile0 < ntiles) {
            const float4* src = (const float4*)(x + (size_t)tile0 * 32 * DDIM);
#pragma unroll
            for (int q = 0; q < 2; q++) {
                int i = q * 512 + tid;
                int r = i >> 5, j = i & 31;
                cp16(s2u(sx) + (u32)((r * 132 + j * 4) * 4), src + r * 32 + j);
            }
        }
        cp_commit();
    }
    __syncthreads();

    for (int tile = bidc; tile < ntiles; tile += nblk) {
        const int row0 = tile * 32;
        if (zcls && tid < 32) ssg[tid] = __ldg(seg + row0 + tid);

        cp_wait0();
        __syncthreads();

        // ---- LN1 from sx -> sa (each warp: 2 rows)
#pragma unroll
        for (int rr = 0; rr < 2; rr++) {
            int rl = wid * 2 + rr;
            float4 xv = *(const float4*)&sx[rl * 132 + lane * 4];
            float s  = warp_sum(xv.x + xv.y + xv.z + xv.w);
            float sq = warp_sum(xv.x * xv.x + xv.y * xv.y + xv.z * xv.z + xv.w * xv.w);
            float m = s * (1.f / 128.f);
            float inv = rsqrtf(sq * (1.f / 128.f) - m * m + LN_EPS);
            float y0 = (xv.x - m) * inv * wv.x + bv.x;
            float y1 = (xv.y - m) * inv * wv.y + bv.y;
            float y2 = (xv.z - m) * inv * wv.z + bv.z;
            float y3 = (xv.w - m) * inv * wv.w + bv.w;
            *(uint2*)(sa + rl * 68 + lane * 2) = make_uint2(pkbf(y0, y1), pkbf(y2, y3));
        }
        __syncthreads();

        // ---- issue prefetch for next tile (lands during GEMM)
        {
            int nxt = tile + nblk;
            if (nxt < ntiles) {
                const float4* src = (const float4*)(x + (size_t)nxt * 32 * DDIM);
#pragma unroll
                for (int q = 0; q < 2; q++) {
                    int i = q * 512 + tid;
                    int r = i >> 5, j = i & 31;
                    cp16(s2u(sx) + (u32)((r * 132 + j * 4) * 4), src + r * 32 + j);
                }
            }
            cp_commit();
        }

        // ---- GEMM: 32 rows x 256 cols (this class's half), K=128
        float acc[4][4];
#pragma unroll
        for (int nt = 0; nt < 4; nt++)
#pragma unroll
            for (int j = 0; j < 4; j++) acc[nt][j] = 0.f;

#pragma unroll
        for (int k0 = 0; k0 < 128; k0 += 16) {
            const int kp = k0 >> 1;
            u32 a[4];
            const u32* pa = sa + (wm * 16 + g) * 68 + kp + t;
            a[0] = pa[0];
            a[2] = pa[4];
            a[1] = pa[8 * 68];
            a[3] = pa[8 * 68 + 4];
#pragma unroll
            for (int nt = 0; nt < 4; nt++) {
                const u32* pb = sw + (wn * 32 + nt * 8 + g) * 68 + kp + t;
                mma_bf16(acc[nt], a, pb[0], pb[4]);
            }
        }

        // ---- bias + SELU
#pragma unroll
        for (int nt = 0; nt < 4; nt++) {
            acc[nt][0] = selu_f(acc[nt][0] + b1r[nt][0]);
            acc[nt][1] = selu_f(acc[nt][1] + b1r[nt][1]);
            acc[nt][2] = selu_f(acc[nt][2] + b1r[nt][0]);
            acc[nt][3] = selu_f(acc[nt][3] + b1r[nt][1]);
        }

        if (zcls == 0) {
            // ---- z1: pack to sz, flush coalesced as uint2
#pragma unroll
            for (int nt = 0; nt < 4; nt++) {
                int r = wm * 16 + g;
                int c2 = wn * 16 + nt * 4 + t;
                sz[r * 130 + c2]       = pkbf(acc[nt][0], acc[nt][1]);
                sz[(r + 8) * 130 + c2] = pkbf(acc[nt][2], acc[nt][3]);
            }
            __syncthreads();
#pragma unroll
            for (int q = 0; q < 4; q++) {
                int i = q * 512 + tid;
                int r = i >> 6, cc = i & 63;
                ((uint2*)zout)[((size_t)(row0 + r) << 6) + cc] =
                    *(const uint2*)&sz[r * 130 + 2 * cc];
            }
        } else {
            // ---- z2: LN2 (cross-warp row reduction), pack, flush, segsum
            float s[2], q[2];
            s[0] = s[1] = q[0] = q[1] = 0.f;
#pragma unroll
            for (int nt = 0; nt < 4; nt++) {
                s[0] += acc[nt][0] + acc[nt][1];
                q[0] += acc[nt][0] * acc[nt][0] + acc[nt][1] * acc[nt][1];
                s[1] += acc[nt][2] + acc[nt][3];
                q[1] += acc[nt][2] * acc[nt][2] + acc[nt][3] * acc[nt][3];
            }
#pragma unroll
            for (int off = 1; off <= 2; off <<= 1)
#pragma unroll
                for (int h = 0; h < 2; h++) {
                    s[h] += __shfl_xor_sync(0xffffffffu, s[h], off);
                    q[h] += __shfl_xor_sync(0xffffffffu, q[h], off);
                }
            if (t == 0) {
#pragma unroll
                for (int h = 0; h < 2; h++) {
                    int r = wm * 16 + g + 8 * h;
                    ps[r * 8 + wn] = s[h];
                    pq[r * 8 + wn] = q[h];
                }
            }
            __syncthreads();
            float mean[2], inv[2];
#pragma unroll
            for (int h = 0; h < 2; h++) {
                int r = wm * 16 + g + 8 * h;
                float S = 0.f, Q = 0.f;
#pragma unroll
                for (int w = 0; w < 8; w++) { S += ps[r * 8 + w]; Q += pq[r * 8 + w]; }
                float m = S * (1.f / 256.f);
                mean[h] = m;
                inv[h] = rsqrtf(Q * (1.f / 256.f) - m * m + LN_EPS);
            }
#pragma unroll
            for (int nt = 0; nt < 4; nt++) {
                int r = wm * 16 + g;
                int c2 = wn * 16 + nt * 4 + t;
                float y0 = (acc[nt][0] - mean[0]) * inv[0] * w2r[nt][0] + b2r[nt][0];
                float y1 = (acc[nt][1] - mean[0]) * inv[0] * w2r[nt][1] + b2r[nt][1];
                float y2 = (acc[nt][2] - mean[1]) * inv[1] * w2r[nt][0] + b2r[nt][0];
                float y3 = (acc[nt][3] - mean[1]) * inv[1] * w2r[nt][1] + b2r[nt][1];
                sz[r * 130 + c2]       = pkbf(y0, y1);
                sz[(r + 8) * 130 + c2] = pkbf(y2, y3);
            }
            __syncthreads();
#pragma unroll
            for (int q2 = 0; q2 < 4; q2++) {
                int i = q2 * 512 + tid;
                int r = i >> 6, cc = i & 63;
                ((uint2*)zout)[((size_t)(row0 + r) << 6) + cc] =
                    *(const uint2*)&sz[r * 130 + 2 * cc];
            }

            // run-length aggregated segment sums (segs sorted)
            {
                int grp = tid >> 8;         // 0,1 -> rows 0-15 / 16-31
                int col = tid & 255;
                int rb = grp * 16;
                float accv = 0.f, cnt = 0.f;
                int cur = ssg[rb];
#pragma unroll 1
                for (int r = rb; r < rb + 16; r++) {
                    int sv = ssg[r];
                    if (sv != cur) {
                        atomicAdd(&segsum[(size_t)cur * HDIM + col], accv);
                        if (col == 0) atomicAdd(&segcnt[cur], cnt);
                        accv = 0.f; cnt = 0.f; cur = sv;
                    }
                    float2 pv = upbf(sz[r * 130 + (col >> 1)]);
                    accv += (col & 1) ? pv.y : pv.x;
                    cnt += 1.f;
                }
                atomicAdd(&segsum[(size_t)cur * HDIM + col], accv);
                if (col == 0) atomicAdd(&segcnt[cur], cnt);
            }
        }
        __syncthreads();
    }
}

// ---------------- Kernel 2: per-(batch,h) gate coefficients ----------------
__global__ void coeff_kernel(const float* __restrict__ sum_r, const float* __restrict__ cnt_r,
                             const float* __restrict__ sum_a, const float* __restrict__ cnt_a,
                             const float* __restrict__ ref_reg, const float* __restrict__ reg_w_pre,
                             const float* __restrict__ beta_ref, const float* __restrict__ beta_alt,
                             const float* __restrict__ gamma,
                             float* __restrict__ cref, float* __restrict__ calt) {
    int b = blockIdx.x;
    int h = threadIdx.x;
    float rw = expf(reg_w_pre[0]) + 0.25f;
    float rcr = 1.f / (__ldg(cnt_r + b) + rw);
    float rca = 1.f / fmaxf(__ldg(cnt_a + b), 1.f);
    int idx = (b << 8) + h;
    float rmf = (__ldg(sum_r + idx) + rw * __ldg(ref_reg + h)) * rcr;
    float amf = __ldg(sum_a + idx) * rca;
    cref[idx] = beta_ref[0] * rmf;
    calt[idx] = beta_alt[0] * amf + gamma[0] * rmf;
}

// ---------------- Kernel 3: persistent gate+GEMM2+residual ----------------
// 512 threads, 2 CTA/SM. W2 bf16 resident. Tile = 64 rows. (R5 winner, unchanged)
#define SW2_U (128 * 132)
#define SG_U  (64 * 132)
#define SM2_BYTES ((SW2_U + SG_U) * 4 + 64 * 4)

__global__ void __launch_bounds__(512, 2)
fwd2_kernel(const float* __restrict__ x, const int* __restrict__ seg,
            const u32* __restrict__ z1, const u32* __restrict__ z2,
            const float* __restrict__ ctab, const float* __restrict__ alpha_p,
            const float* __restrict__ w2, const float* __restrict__ b2,
            float* __restrict__ out, int ntiles) {
    extern __shared__ float smf[];
    u32* sw = (u32*)smf;            // [128 n][132] bf16 k-pairs of W2
    u32* sg = sw + SW2_U;           // [64 m][132]  gated activations
    int* ssg = (int*)(sg + SG_U);   // [64]

    const int tid = threadIdx.x;
    const int lane = tid & 31;
    const int wid = tid >> 5;
    const int g = lane >> 2;
    const int t = lane & 3;
    const int wm = wid & 3;    // 4 row-groups of 16
    const int wn = wid >> 2;   // 4 col-groups of 32

    for (int i = tid; i < 128 * 128; i += 512) {
        int kp = i >> 7;
        int n = i & 127;
        float v0 = __ldg(w2 + (size_t)(2 * kp) * DDIM + n);
        float v1 = __ldg(w2 + (size_t)(2 * kp + 1) * DDIM + n);
        sw[n * 132 + kp] = pkbf(v0, v1);
    }
    float b2r[4][2];
#pragma unroll
    for (int nt = 0; nt < 4; nt++) {
        int col = wn * 32 + nt * 8 + 2 * t;
        b2r[nt][0] = __ldg(b2 + col);
        b2r[nt][1] = __ldg(b2 + col + 1);
    }
    const float alpha = __ldg(alpha_p);
    __syncthreads();

    const uint2* z1v2 = (const uint2*)z1;
    const uint2* z2v2 = (const uint2*)z2;
    const float4* ctab4 = (const float4*)ctab;
    const float2* x2 = (const float2*)x;
    float2* out2 = (float2*)out;

    for (int tile = blockIdx.x; tile < ntiles; tile += gridDim.x) {
        const int row0 = tile * 64;
        if (tid < 64) ssg[tid] = __ldg(seg + row0 + tid);
        __syncthreads();

#pragma unroll 4
        for (int i = tid; i < 64 * 64; i += 512) {
            int r = i >> 6, cc = i & 63;
            size_t gidx = ((size_t)(row0 + r) << 6) + cc;
            uint2 z1p = __ldg(z1v2 + gidx);
            uint2 z2p = __ldg(z2v2 + gidx);
            float4 c4 = __ldg(ctab4 + (((size_t)ssg[r]) << 6) + cc);
            float2 z1a = upbf(z1p.x), z1b = upbf(z1p.y);
            float2 z2a = upbf(z2p.x), z2b = upbf(z2p.y);
            float g0 = z1a.x * fmaf(z2a.x, alpha, 1.f + c4.x);
            float g1 = z1a.y * fmaf(z2a.y, alpha, 1.f + c4.y);
            float g2 = z1b.x * fmaf(z2b.x, alpha, 1.f + c4.z);
            float g3 = z1b.y * fmaf(z2b.y, alpha, 1.f + c4.w);
            *(uint2*)&sg[r * 132 + 2 * cc] = make_uint2(pkbf(g0, g1), pkbf(g2, g3));
        }
        __syncthreads();

        float acc[4][4];
#pragma unroll
        for (int nt = 0; nt < 4; nt++)
#pragma unroll
            for (int j = 0; j < 4; j++) acc[nt][j] = 0.f;

#pragma unroll
        for (int k0 = 0; k0 < 256; k0 += 16) {
            const int kp = k0 >> 1;
            u32 a[4];
            const u32* pa = sg + (wm * 16 + g) * 132 + kp + t;
            a[0] = pa[0];
            a[2] = pa[4];
            a[1] = pa[8 * 132];
            a[3] = pa[8 * 132 + 4];
#pragma unroll
            for (int nt = 0; nt < 4; nt++) {
                const u32* pb = sw + (wn * 32 + nt * 8 + g) * 132 + kp + t;
                mma_bf16(acc[nt], a, pb[0], pb[4]);
            }
        }

#pragma unroll
        for (int nt = 0; nt < 4; nt++) {
            int col2 = (wn * 32 + nt * 8 + 2 * t) >> 1;
            size_t rowA = (size_t)(row0 + wm * 16 + g);
            size_t rowB = rowA + 8;
            float2 xa = __ldg(x2 + rowA * 64 + col2);
            float2 xb = __ldg(x2 + rowB * 64 + col2);
            float2 oa, ob;
            oa.x = xa.x + acc[nt][0] + b2r[nt][0];
            oa.y = xa.y + acc[nt][1] + b2r[nt][1];
            ob.x = xb.x + acc[nt][2] + b2r[nt][0];
            ob.y = xb.y + acc[nt][3] + b2r[nt][1];
            out2[rowA * 64 + col2] = oa;
            out2[rowB * 64 + col2] = ob;
        }
        __syncthreads();
    }
}

// ---------------- Launch ----------------
extern "C" void kernel_launch(void* const* d_in, const int* in_sizes, int n_in,
                              void* d_out, int out_size) {
    const float* ref_flat = (const float*)d_in[0];
    const float* alt_flat = (const float*)d_in[1];
    const int*   ref_seg  = (const int*)d_in[2];
    const int*   alt_seg  = (const int*)d_in[3];
    const float* norm1_w  = (const float*)d_in[4];
    const float* norm1_b  = (const float*)d_in[5];
    const float* w1_ref   = (const float*)d_in[6];
    const float* b1_ref   = (const float*)d_in[7];
    const float* w1_alt   = (const float*)d_in[8];
    const float* b1_alt   = (const float*)d_in[9];
    const float* norm2_w  = (const float*)d_in[10];
    const float* norm2_b  = (const float*)d_in[11];
    const float* alpha_ref = (const float*)d_in[12];
    const float* alpha_alt = (const float*)d_in[13];
    const float* beta_ref  = (const float*)d_in[14];
    const float* beta_alt  = (const float*)d_in[15];
    const float* gamma     = (const float*)d_in[16];
    const float* ref_regularizer = (const float*)d_in[17];
    const float* reg_w_pre = (const float*)d_in[18];
    const float* w2_ref    = (const float*)d_in[19];
    const float* b2_ref    = (const float*)d_in[20];
    const float* w2_alt    = (const float*)d_in[21];
    const float* b2_alt    = (const float*)d_in[22];

    float* out_r = (float*)d_out;
    float* out_a = out_r + (size_t)NREF * DDIM;

    u32 *pz1r, *pz2r, *pz1a, *pz2a;
    float *psr, *psa, *pcr, *pca, *pcref, *pcalt;
    cudaGetSymbolAddress((void**)&pz1r, g_z1_ref);
    cudaGetSymbolAddress((void**)&pz2r, g_z2_ref);
    cudaGetSymbolAddress((void**)&pz1a, g_z1_alt);
    cudaGetSymbolAddress((void**)&pz2a, g_z2_alt);
    cudaGetSymbolAddress((void**)&psr,  g_sum_ref);
    cudaGetSymbolAddress((void**)&psa,  g_sum_alt);
    cudaGetSymbolAddress((void**)&pcr,  g_cnt_ref);
    cudaGetSymbolAddress((void**)&pca,  g_cnt_alt);
    cudaGetSymbolAddress((void**)&pcref, g_cref);
    cudaGetSymbolAddress((void**)&pcalt, g_calt);

    int sm_count = 148;
    cudaDeviceGetAttribute(&sm_count, cudaDevAttrMultiProcessorCount, 0);

    cudaFuncSetAttribute(fwd1_kernel, cudaFuncAttributeMaxDynamicSharedMemorySize, SM1_BYTES);
    cudaFuncSetAttribute(fwd2_kernel, cudaFuncAttributeMaxDynamicSharedMemorySize, SM2_BYTES);

    zero_kernel<<<(BSEG * HDIM + 255) / 256, 256>>>(psr, psa, pcr, pca);

    fwd1_kernel<<<2 * sm_count, 512, SM1_BYTES>>>(ref_flat, ref_seg, norm1_w, norm1_b,
                                                  w1_ref, b1_ref, norm2_w, norm2_b,
                                                  pz1r, pz2r, psr, pcr, NREF / 32);
    fwd1_kernel<<<2 * sm_count, 512, SM1_BYTES>>>(alt_flat, alt_seg, norm1_w, norm1_b,
                                                  w1_alt, b1_alt, norm2_w, norm2_b,
                                                  pz1a, pz2a, psa, pca, NALT / 32);

    coeff_kernel<<<BSEG, 256>>>(psr, pcr, psa, pca,
                                ref_regularizer, reg_w_pre,
                                beta_ref, beta_alt, gamma,
                                pcref, pcalt);

    fwd2_kernel<<<2 * sm_count, 512, SM2_BYTES>>>(ref_flat, ref_seg, pz1r, pz2r,
                                                  pcref, alpha_ref, w2_ref, b2_ref,
                                                  out_r, NREF / 64);
    fwd2_kernel<<<2 * sm_count, 512, SM2_BYTES>>>(alt_flat, alt_seg, pz1a, pz2a,
                                                  pcalt, alpha_alt, w2_alt, b2_alt,
                                                  out_a, NALT / 64);
}